// round 1
// baseline (speedup 1.0000x reference)
#include <cuda_runtime.h>

#define NB   8
#define NSEQ 2048
#define ND   128
#define NH   8
#define NHD  16
#define NROWS (NB*NSEQ)     /* 16384 */
#define NZH   (NB*NH)       /* 64    */

// ---------------- scratch (device globals; no allocation allowed) -----------
__device__ float g_Q[NZH*NSEQ*NHD];     // Q after proj(+rope), [b][h][n][hd]
__device__ float g_K[NZH*NSEQ*NHD];
__device__ float g_V[NZH*NSEQ*NHD];
__device__ float g_O[NROWS*ND];         // attention out, [b][n][h*hd]
__device__ float g_tab[NSEQ*8*3];       // per (n,j): cos, sin, scale

// ---------------- tiny asm helpers -----------------------------------------
__device__ __forceinline__ unsigned long long pk2(float x, float y){
  unsigned long long r; asm("mov.b64 %0, {%1,%2};" : "=l"(r) : "f"(x), "f"(y)); return r; }
__device__ __forceinline__ float2 upk2(unsigned long long v){
  float2 r; asm("mov.b64 {%0,%1}, %2;" : "=f"(r.x), "=f"(r.y) : "l"(v)); return r; }
__device__ __forceinline__ void ffma2(unsigned long long& d, unsigned long long a, unsigned long long b){
  asm("fma.rn.f32x2 %0, %1, %2, %0;" : "+l"(d) : "l"(a), "l"(b)); }
__device__ __forceinline__ unsigned long long fadd2(unsigned long long a, unsigned long long b){
  unsigned long long r; asm("add.rn.f32x2 %0, %1, %2;" : "=l"(r) : "l"(a), "l"(b)); return r; }
__device__ __forceinline__ float ex2f_(float x){ float y; asm("ex2.approx.f32 %0, %1;" : "=f"(y) : "f"(x)); return y; }
__device__ __forceinline__ float rcpf_(float x){ float y; asm("rcp.approx.f32 %0, %1;" : "=f"(y) : "f"(x)); return y; }

// log(400)/log(50)/sqrt(16)
#define LOGIT_SCALE 0.38288786755f
#define LOG2E       1.4426950408889634f

// ---------------- rope tables (double precision, trivial cost) --------------
__global__ void rope_table_kernel(){
  int n = blockIdx.x*blockDim.x + threadIdx.x;
  if (n >= NSEQ) return;
  double t = (double)n;
  #pragma unroll
  for (int j=0;j<8;j++){
    double inv = exp(-((double)j/8.0) * log(10000.0));
    double f   = t * inv;
    double sc  = (2.0*j + 0.4*16.0) / (1.4*16.0);
    double pw  = (t - 1024.0) / 512.0;
    double scl = exp(pw * log(sc));
    int o = (n*8 + j)*3;
    g_tab[o+0] = (float)cos(f);
    g_tab[o+1] = (float)sin(f);
    g_tab[o+2] = (float)scl;
  }
}

// ---------------- tiled SGEMM: C[16384x128] = A[16384x128] @ W[128x128]^T ---
// MODE 0: row-major C.  MODE 1: scatter to [b][h][n][hd].
template<int MODE>
__device__ __forceinline__ void gemm128(const float* __restrict__ A,
                                        const float* __restrict__ W,
                                        float* __restrict__ C){
  __shared__ float As[16][68];
  __shared__ float Ws[16][132];
  const int tid = threadIdx.x;
  const int m0  = blockIdx.x * 64;
  const int tm  = tid >> 4, tn = tid & 15;
  float acc[8][8];
  #pragma unroll
  for (int i=0;i<8;i++)
    #pragma unroll
    for (int j=0;j<8;j++) acc[i][j]=0.f;

  const int ar = tid >> 1, ac = (tid & 1) * 8;
  for (int k0=0;k0<128;k0+=16){
    const float4* ap = (const float4*)(A + (size_t)(m0+ar)*128 + k0 + ac);
    float4 a0 = ap[0], a1 = ap[1];
    As[ac+0][ar]=a0.x; As[ac+1][ar]=a0.y; As[ac+2][ar]=a0.z; As[ac+3][ar]=a0.w;
    As[ac+4][ar]=a1.x; As[ac+5][ar]=a1.y; As[ac+6][ar]=a1.z; As[ac+7][ar]=a1.w;
    const float4* wp = (const float4*)(W + (size_t)tid*128 + k0);
    float4 w0=wp[0], w1=wp[1], w2=wp[2], w3=wp[3];
    Ws[ 0][tid]=w0.x; Ws[ 1][tid]=w0.y; Ws[ 2][tid]=w0.z; Ws[ 3][tid]=w0.w;
    Ws[ 4][tid]=w1.x; Ws[ 5][tid]=w1.y; Ws[ 6][tid]=w1.z; Ws[ 7][tid]=w1.w;
    Ws[ 8][tid]=w2.x; Ws[ 9][tid]=w2.y; Ws[10][tid]=w2.z; Ws[11][tid]=w2.w;
    Ws[12][tid]=w3.x; Ws[13][tid]=w3.y; Ws[14][tid]=w3.z; Ws[15][tid]=w3.w;
    __syncthreads();
    #pragma unroll
    for (int kk=0;kk<16;kk++){
      float a[8], wv[8];
      #pragma unroll
      for (int i=0;i<8;i++) a[i]  = As[kk][tm*8+i];
      #pragma unroll
      for (int j=0;j<8;j++) wv[j] = Ws[kk][tn*8+j];
      #pragma unroll
      for (int i=0;i<8;i++)
        #pragma unroll
        for (int j=0;j<8;j++)
          acc[i][j] = fmaf(a[i], wv[j], acc[i][j]);
    }
    __syncthreads();
  }

  if (MODE == 0){
    #pragma unroll
    for (int i=0;i<8;i++){
      int row = m0 + tm*8 + i;
      float4* c4 = (float4*)(C + (size_t)row*128 + tn*8);
      c4[0] = make_float4(acc[i][0],acc[i][1],acc[i][2],acc[i][3]);
      c4[1] = make_float4(acc[i][4],acc[i][5],acc[i][6],acc[i][7]);
    }
  } else {
    const int h = tn >> 1, hd0 = (tn & 1)*8;
    #pragma unroll
    for (int i=0;i<8;i++){
      int row = m0 + tm*8 + i;
      int bb = row >> 11, nn = row & 2047;
      float4* c4 = (float4*)(C + (((size_t)bb*NH + h)*NSEQ + nn)*NHD + hd0);
      c4[0] = make_float4(acc[i][0],acc[i][1],acc[i][2],acc[i][3]);
      c4[1] = make_float4(acc[i][4],acc[i][5],acc[i][6],acc[i][7]);
    }
  }
}

__global__ void __launch_bounds__(128) qkv_kernel(const float* __restrict__ q,
                                                  const float* __restrict__ k,
                                                  const float* __restrict__ v,
                                                  const float* __restrict__ Wq,
                                                  const float* __restrict__ Wk,
                                                  const float* __restrict__ Wv){
  int w = blockIdx.z;
  const float* A = (w==0) ? q  : (w==1) ? k  : v;
  const float* W = (w==0) ? Wq : (w==1) ? Wk : Wv;
  float*       C = (w==0) ? g_Q : (w==1) ? g_K : g_V;
  gemm128<1>(A, W, C);
}

__global__ void __launch_bounds__(128) outproj_kernel(const float* __restrict__ Wout,
                                                      float* __restrict__ out){
  gemm128<0>(g_O, Wout, out);
}

// ---------------- RoPE-xpos applied in place on g_Q / g_K -------------------
__global__ void __launch_bounds__(128) rope_apply_kernel(){
  int r = blockIdx.x*128 + threadIdx.x;      // r in [0, NZH*NSEQ)
  int n = r & (NSEQ-1);
  float* Q = g_Q + (size_t)r*NHD;
  float* K = g_K + (size_t)r*NHD;
  float qv[16], kv[16];
  float4* Q4=(float4*)Q; float4* K4=(float4*)K;
  #pragma unroll
  for (int i=0;i<4;i++){
    float4 a=Q4[i]; qv[4*i]=a.x; qv[4*i+1]=a.y; qv[4*i+2]=a.z; qv[4*i+3]=a.w;
    float4 b=K4[i]; kv[4*i]=b.x; kv[4*i+1]=b.y; kv[4*i+2]=b.z; kv[4*i+3]=b.w;
  }
  const float* tb = g_tab + n*24;
  #pragma unroll
  for (int j=0;j<8;j++){
    float c=tb[j*3+0], s=tb[j*3+1], scl=tb[j*3+2];
    float inv = 1.0f/scl;
    float qe=qv[2*j], qo=qv[2*j+1];
    qv[2*j]   = (qe*c - qo*s)*scl;
    qv[2*j+1] = (qo*c + qe*s)*scl;
    float ke=kv[2*j], ko=kv[2*j+1];
    kv[2*j]   = (ke*c - ko*s)*inv;
    kv[2*j+1] = (ko*c + ke*s)*inv;
  }
  #pragma unroll
  for (int i=0;i<4;i++){
    Q4[i] = make_float4(qv[4*i],qv[4*i+1],qv[4*i+2],qv[4*i+3]);
    K4[i] = make_float4(kv[4*i],kv[4*i+1],kv[4*i+2],kv[4*i+3]);
  }
}

// ---------------- attention: single pass (logits bounded by tanh clip) ------
// grid (NSEQ/256, NZH), 128 threads, 2 queries/thread.
__global__ void __launch_bounds__(128) attn_kernel(const unsigned char* __restrict__ mask){
  const int z = blockIdx.y;
  const int b = z >> 3;
  const int h = z & 7;
  const int t = threadIdx.x;
  const int q0 = blockIdx.x * 256 + t;
  const int q1 = q0 + 128;
  const float* Qb = g_Q + (size_t)z * NSEQ * NHD;
  const float* Kb = g_K + (size_t)z * NSEQ * NHD;
  const float* Vb = g_V + (size_t)z * NSEQ * NHD;

  __shared__ float Ks[128][20];
  __shared__ float Vs[128][20];
  __shared__ float Ms[128];

  unsigned long long qp0[8], qp1[8], num0[8], num1[8];
  {
    const ulonglong2* qa = (const ulonglong2*)(Qb + (size_t)q0*NHD);
    #pragma unroll
    for (int i=0;i<4;i++){ ulonglong2 u = qa[i]; qp0[2*i]=u.x; qp0[2*i+1]=u.y; }
    const ulonglong2* qc = (const ulonglong2*)(Qb + (size_t)q1*NHD);
    #pragma unroll
    for (int i=0;i<4;i++){ ulonglong2 u = qc[i]; qp1[2*i]=u.x; qp1[2*i+1]=u.y; }
  }
  #pragma unroll
  for (int i=0;i<8;i++){ num0[i]=0ull; num1[i]=0ull; }
  float den0=0.f, den1=0.f;
  const unsigned char* mrow = mask + b*NSEQ;

  const float C_EX  = LOGIT_SCALE * 2.0f * LOG2E;  // ex2 arg per unit dot
  const float C_OUT = 10.0f * LOG2E;               // CLIP * log2(e)

  for (int kt=0; kt<NSEQ; kt+=128){
    const float4* ksrc = (const float4*)(Kb + (size_t)kt*NHD);
    const float4* vsrc = (const float4*)(Vb + (size_t)kt*NHD);
    #pragma unroll
    for (int i=0;i<4;i++){
      int f = t + i*128;
      int kr = f >> 2, cc = (f & 3) << 2;
      *(float4*)&Ks[kr][cc] = ksrc[f];
      *(float4*)&Vs[kr][cc] = vsrc[f];
    }
    Ms[t] = mrow[kt + t] ? 0.0f : 1.0f;
    __syncthreads();

    #pragma unroll 2
    for (int k=0;k<128;k++){
      const ulonglong2* kr2 = (const ulonglong2*)&Ks[k][0];
      ulonglong2 kA = kr2[0], kB = kr2[1], kC = kr2[2], kD = kr2[3];
      unsigned long long d0a=0ull, d0b=0ull, d1a=0ull, d1b=0ull;
      ffma2(d0a, qp0[0], kA.x); ffma2(d0b, qp0[1], kA.y);
      ffma2(d1a, qp1[0], kA.x); ffma2(d1b, qp1[1], kA.y);
      ffma2(d0a, qp0[2], kB.x); ffma2(d0b, qp0[3], kB.y);
      ffma2(d1a, qp1[2], kB.x); ffma2(d1b, qp1[3], kB.y);
      ffma2(d0a, qp0[4], kC.x); ffma2(d0b, qp0[5], kC.y);
      ffma2(d1a, qp1[4], kC.x); ffma2(d1b, qp1[5], kC.y);
      ffma2(d0a, qp0[6], kD.x); ffma2(d0b, qp0[7], kD.y);
      ffma2(d1a, qp1[6], kD.x); ffma2(d1b, qp1[7], kD.y);
      float2 f0 = upk2(fadd2(d0a, d0b));
      float2 f1 = upk2(fadd2(d1a, d1b));
      float dot0 = f0.x + f0.y, dot1 = f1.x + f1.y;
      float m = Ms[k];
      // p = exp(10 * tanh(dot * LOGIT_SCALE)); tanh via exact e^{2x} formula.
      float u0 = ex2f_(dot0 * C_EX);
      float u1 = ex2f_(dot1 * C_EX);
      float th0 = 1.0f - 2.0f*rcpf_(u0 + 1.0f);
      float th1 = 1.0f - 2.0f*rcpf_(u1 + 1.0f);
      float p0 = ex2f_(th0 * C_OUT) * m;
      float p1 = ex2f_(th1 * C_OUT) * m;
      den0 += p0; den1 += p1;
      const ulonglong2* vr2 = (const ulonglong2*)&Vs[k][0];
      ulonglong2 vA = vr2[0], vB = vr2[1], vC = vr2[2], vD = vr2[3];
      unsigned long long pp0 = pk2(p0,p0), pp1 = pk2(p1,p1);
      ffma2(num0[0], pp0, vA.x); ffma2(num0[1], pp0, vA.y);
      ffma2(num0[2], pp0, vB.x); ffma2(num0[3], pp0, vB.y);
      ffma2(num0[4], pp0, vC.x); ffma2(num0[5], pp0, vC.y);
      ffma2(num0[6], pp0, vD.x); ffma2(num0[7], pp0, vD.y);
      ffma2(num1[0], pp1, vA.x); ffma2(num1[1], pp1, vA.y);
      ffma2(num1[2], pp1, vB.x); ffma2(num1[3], pp1, vB.y);
      ffma2(num1[4], pp1, vC.x); ffma2(num1[5], pp1, vC.y);
      ffma2(num1[6], pp1, vD.x); ffma2(num1[7], pp1, vD.y);
    }
    __syncthreads();
  }

  // epilogue: o = num / den, stored to [b][n][h*16+hd]
  {
    float r = rcpf_(den0); r = r*(2.0f - den0*r);
    float4* o4 = (float4*)(g_O + ((size_t)b*NSEQ + q0)*ND + h*NHD);
    #pragma unroll
    for (int i=0;i<4;i++){
      float2 e0 = upk2(num0[2*i]);
      float2 e1 = upk2(num0[2*i+1]);
      o4[i] = make_float4(e0.x*r, e0.y*r, e1.x*r, e1.y*r);
    }
  }
  {
    float r = rcpf_(den1); r = r*(2.0f - den1*r);
    float4* o4 = (float4*)(g_O + ((size_t)b*NSEQ + q1)*ND + h*NHD);
    #pragma unroll
    for (int i=0;i<4;i++){
      float2 e0 = upk2(num1[2*i]);
      float2 e1 = upk2(num1[2*i+1]);
      o4[i] = make_float4(e0.x*r, e0.y*r, e1.x*r, e1.y*r);
    }
  }
}

// ---------------- launch -----------------------------------------------------
extern "C" void kernel_launch(void* const* d_in, const int* in_sizes, int n_in,
                              void* d_out, int out_size){
  const float* q    = (const float*)d_in[0];
  const float* k    = (const float*)d_in[1];
  const float* v    = (const float*)d_in[2];
  const float* Wq   = (const float*)d_in[3];
  const float* Wk   = (const float*)d_in[4];
  const float* Wv   = (const float*)d_in[5];
  const float* Wout = (const float*)d_in[6];
  const unsigned char* mask = (const unsigned char*)d_in[7];
  float* out = (float*)d_out;

  rope_table_kernel<<<16,128>>>();
  qkv_kernel<<<dim3(NROWS/64,1,3),128>>>(q,k,v,Wq,Wk,Wv);
  rope_apply_kernel<<<(NZH*NSEQ)/128,128>>>();
  attn_kernel<<<dim3(NSEQ/256, NZH),128>>>(mask);
  outproj_kernel<<<dim3(NROWS/64,1,1),128>>>(Wout, out);
}

// round 2
// speedup vs baseline: 1.0715x; 1.0715x over previous
#include <cuda_runtime.h>

#define NB   8
#define NSEQ 2048
#define ND   128
#define NH   8
#define NHD  16
#define NROWS (NB*NSEQ)     /* 16384 */
#define NZH   (NB*NH)       /* 64    */

// ---------------- scratch (device globals; no allocation allowed) -----------
__device__ float g_Q[NZH*NSEQ*NHD];     // Q after proj+rope, [b][h][n][hd]
__device__ float g_K[NZH*NSEQ*NHD];
__device__ float g_V[NZH*NSEQ*NHD];
__device__ float g_O[NROWS*ND];         // attention out, [b][n][h*hd]
__device__ float g_tab[NSEQ*8*3];       // per (n,j): cos, sin, scale

// ---------------- tiny asm helpers -----------------------------------------
__device__ __forceinline__ unsigned long long pk2(float x, float y){
  unsigned long long r; asm("mov.b64 %0, {%1,%2};" : "=l"(r) : "f"(x), "f"(y)); return r; }
__device__ __forceinline__ float2 upk2(unsigned long long v){
  float2 r; asm("mov.b64 {%0,%1}, %2;" : "=f"(r.x), "=f"(r.y) : "l"(v)); return r; }
__device__ __forceinline__ void ffma2(unsigned long long& d, unsigned long long a, unsigned long long b){
  asm("fma.rn.f32x2 %0, %1, %2, %0;" : "+l"(d) : "l"(a), "l"(b)); }
__device__ __forceinline__ unsigned long long fadd2(unsigned long long a, unsigned long long b){
  unsigned long long r; asm("add.rn.f32x2 %0, %1, %2;" : "=l"(r) : "l"(a), "l"(b)); return r; }
__device__ __forceinline__ float ex2f_(float x){ float y; asm("ex2.approx.f32 %0, %1;" : "=f"(y) : "f"(x)); return y; }
__device__ __forceinline__ float rcpf_(float x){ float y; asm("rcp.approx.f32 %0, %1;" : "=f"(y) : "f"(x)); return y; }

// log(400)/log(50)/sqrt(16)
#define LOGIT_SCALE 0.38288786755f
#define LOG2E       1.4426950408889634f

// ---------------- rope tables (double precision, trivial cost) --------------
__global__ void rope_table_kernel(){
  int n = blockIdx.x*blockDim.x + threadIdx.x;
  if (n >= NSEQ) return;
  double t = (double)n;
  #pragma unroll
  for (int j=0;j<8;j++){
    double inv = exp(-((double)j/8.0) * log(10000.0));
    double f   = t * inv;
    double sc  = (2.0*j + 0.4*16.0) / (1.4*16.0);
    double pw  = (t - 1024.0) / 512.0;
    double scl = exp(pw * log(sc));
    int o = (n*8 + j)*3;
    g_tab[o+0] = (float)cos(f);
    g_tab[o+1] = (float)sin(f);
    g_tab[o+2] = (float)scl;
  }
}

// ---------------- tiled SGEMM: C[16384x128] = A[16384x128] @ W[128x128]^T ---
// MODE 0: row-major C.  MODE 1: scatter to [b][h][n][hd], rope: 0=none,1=Q,2=K.
template<int MODE>
__device__ __forceinline__ void gemm128(const float* __restrict__ A,
                                        const float* __restrict__ W,
                                        float* __restrict__ C, int rope){
  __shared__ float As[16][68];
  __shared__ float Ws[16][132];
  const int tid = threadIdx.x;
  const int m0  = blockIdx.x * 64;
  const int tm  = tid >> 4, tn = tid & 15;

  unsigned long long acc2[8][4];
  #pragma unroll
  for (int i=0;i<8;i++)
    #pragma unroll
    for (int j=0;j<4;j++) acc2[i][j]=0ull;

  const int ar = tid >> 1, ac = (tid & 1) * 8;
  for (int k0=0;k0<128;k0+=16){
    const float4* ap = (const float4*)(A + (size_t)(m0+ar)*128 + k0 + ac);
    float4 a0 = ap[0], a1 = ap[1];
    As[ac+0][ar]=a0.x; As[ac+1][ar]=a0.y; As[ac+2][ar]=a0.z; As[ac+3][ar]=a0.w;
    As[ac+4][ar]=a1.x; As[ac+5][ar]=a1.y; As[ac+6][ar]=a1.z; As[ac+7][ar]=a1.w;
    const float4* wp = (const float4*)(W + (size_t)tid*128 + k0);
    float4 w0=wp[0], w1=wp[1], w2=wp[2], w3=wp[3];
    Ws[ 0][tid]=w0.x; Ws[ 1][tid]=w0.y; Ws[ 2][tid]=w0.z; Ws[ 3][tid]=w0.w;
    Ws[ 4][tid]=w1.x; Ws[ 5][tid]=w1.y; Ws[ 6][tid]=w1.z; Ws[ 7][tid]=w1.w;
    Ws[ 8][tid]=w2.x; Ws[ 9][tid]=w2.y; Ws[10][tid]=w2.z; Ws[11][tid]=w2.w;
    Ws[12][tid]=w3.x; Ws[13][tid]=w3.y; Ws[14][tid]=w3.z; Ws[15][tid]=w3.w;
    __syncthreads();
    #pragma unroll
    for (int kk=0;kk<16;kk++){
      float av[8];
      #pragma unroll
      for (int i=0;i<8;i++) av[i] = As[kk][tm*8+i];
      const ulonglong2* wr = (const ulonglong2*)&Ws[kk][tn*8];
      ulonglong2 w01 = wr[0], w23 = wr[1];
      #pragma unroll
      for (int i=0;i<8;i++){
        unsigned long long aa = pk2(av[i], av[i]);
        ffma2(acc2[i][0], aa, w01.x);
        ffma2(acc2[i][1], aa, w01.y);
        ffma2(acc2[i][2], aa, w23.x);
        ffma2(acc2[i][3], aa, w23.y);
      }
    }
    __syncthreads();
  }

  if (MODE == 0){
    #pragma unroll
    for (int i=0;i<8;i++){
      int row = m0 + tm*8 + i;
      float2 e0=upk2(acc2[i][0]), e1=upk2(acc2[i][1]);
      float2 e2=upk2(acc2[i][2]), e3=upk2(acc2[i][3]);
      float4* c4 = (float4*)(C + (size_t)row*128 + tn*8);
      c4[0] = make_float4(e0.x,e0.y,e1.x,e1.y);
      c4[1] = make_float4(e2.x,e2.y,e3.x,e3.y);
    }
  } else {
    const int h = tn >> 1, hd0 = (tn & 1)*8;
    const int j0 = hd0 >> 1;              // first rope pair index (of 8)
    #pragma unroll
    for (int i=0;i<8;i++){
      int row = m0 + tm*8 + i;
      int bb = row >> 11, nn = row & 2047;
      float vbuf[8];
      {
        float2 e0=upk2(acc2[i][0]), e1=upk2(acc2[i][1]);
        float2 e2=upk2(acc2[i][2]), e3=upk2(acc2[i][3]);
        vbuf[0]=e0.x; vbuf[1]=e0.y; vbuf[2]=e1.x; vbuf[3]=e1.y;
        vbuf[4]=e2.x; vbuf[5]=e2.y; vbuf[6]=e3.x; vbuf[7]=e3.y;
      }
      if (rope != 0){
        const float* tb = g_tab + nn*24 + j0*3;
        #pragma unroll
        for (int jj=0;jj<4;jj++){
          float c=tb[jj*3+0], s=tb[jj*3+1], scl=tb[jj*3+2];
          float sc = (rope==1) ? scl : (1.0f/scl);
          float e=vbuf[2*jj], o=vbuf[2*jj+1];
          vbuf[2*jj]   = (e*c - o*s)*sc;
          vbuf[2*jj+1] = (o*c + e*s)*sc;
        }
      }
      float4* c4 = (float4*)(C + (((size_t)bb*NH + h)*NSEQ + nn)*NHD + hd0);
      c4[0] = make_float4(vbuf[0],vbuf[1],vbuf[2],vbuf[3]);
      c4[1] = make_float4(vbuf[4],vbuf[5],vbuf[6],vbuf[7]);
    }
  }
}

__global__ void __launch_bounds__(128) qkv_kernel(const float* __restrict__ q,
                                                  const float* __restrict__ k,
                                                  const float* __restrict__ v,
                                                  const float* __restrict__ Wq,
                                                  const float* __restrict__ Wk,
                                                  const float* __restrict__ Wv){
  int w = blockIdx.z;
  const float* A = (w==0) ? q  : (w==1) ? k  : v;
  const float* W = (w==0) ? Wq : (w==1) ? Wk : Wv;
  float*       C = (w==0) ? g_Q : (w==1) ? g_K : g_V;
  int rope = (w==0) ? 1 : (w==1) ? 2 : 0;
  gemm128<1>(A, W, C, rope);
}

__global__ void __launch_bounds__(128) outproj_kernel(const float* __restrict__ Wout,
                                                      float* __restrict__ out){
  gemm128<0>(g_O, Wout, out, 0);
}

// ---------------- attention: single pass (logits bounded by tanh clip) ------
// grid (NSEQ/128, NZH), 128 threads, 1 query/thread.
__global__ void __launch_bounds__(128) attn_kernel(const unsigned char* __restrict__ mask){
  const int z = blockIdx.y;
  const int b = z >> 3;
  const int h = z & 7;
  const int t = threadIdx.x;
  const int q0 = blockIdx.x * 128 + t;
  const float* Qb = g_Q + (size_t)z * NSEQ * NHD;
  const float* Kb = g_K + (size_t)z * NSEQ * NHD;
  const float* Vb = g_V + (size_t)z * NSEQ * NHD;

  __shared__ float Ks[128][20];
  __shared__ float Vs[128][20];
  __shared__ float Ms[128];

  unsigned long long qp[8], num[8];
  {
    const ulonglong2* qa = (const ulonglong2*)(Qb + (size_t)q0*NHD);
    #pragma unroll
    for (int i=0;i<4;i++){ ulonglong2 u = qa[i]; qp[2*i]=u.x; qp[2*i+1]=u.y; }
  }
  #pragma unroll
  for (int i=0;i<8;i++) num[i]=0ull;
  float den=0.f;
  const unsigned char* mrow = mask + b*NSEQ;

  const float C_EX  = LOGIT_SCALE * 2.0f * LOG2E;  // ex2 arg per unit dot
  const float C_OUT = 10.0f * LOG2E;               // CLIP * log2(e)

  for (int kt=0; kt<NSEQ; kt+=128){
    const float4* ksrc = (const float4*)(Kb + (size_t)kt*NHD);
    const float4* vsrc = (const float4*)(Vb + (size_t)kt*NHD);
    #pragma unroll
    for (int i=0;i<4;i++){
      int f = t + i*128;
      int kr = f >> 2, cc = (f & 3) << 2;
      *(float4*)&Ks[kr][cc] = ksrc[f];
      *(float4*)&Vs[kr][cc] = vsrc[f];
    }
    Ms[t] = mrow[kt + t] ? 0.0f : 1.0f;
    __syncthreads();

    #pragma unroll 4
    for (int k=0;k<128;k++){
      const ulonglong2* kr2 = (const ulonglong2*)&Ks[k][0];
      ulonglong2 kA = kr2[0], kB = kr2[1], kC = kr2[2], kD = kr2[3];
      unsigned long long d0a=0ull, d0b=0ull;
      ffma2(d0a, qp[0], kA.x); ffma2(d0b, qp[1], kA.y);
      ffma2(d0a, qp[2], kB.x); ffma2(d0b, qp[3], kB.y);
      ffma2(d0a, qp[4], kC.x); ffma2(d0b, qp[5], kC.y);
      ffma2(d0a, qp[6], kD.x); ffma2(d0b, qp[7], kD.y);
      float2 f0 = upk2(fadd2(d0a, d0b));
      float dot0 = f0.x + f0.y;
      // p = exp(10 * tanh(dot * LOGIT_SCALE)); tanh via exact e^{2x} formula.
      float e0 = ex2f_(dot0 * C_EX);
      float r0 = rcpf_(e0 + 1.0f);
      float p0 = ex2f_(fmaf(r0, -2.0f*C_OUT, C_OUT)) * Ms[k];
      den += p0;
      const ulonglong2* vr2 = (const ulonglong2*)&Vs[k][0];
      ulonglong2 vA = vr2[0], vB = vr2[1], vC = vr2[2], vD = vr2[3];
      unsigned long long pp0 = pk2(p0,p0);
      ffma2(num[0], pp0, vA.x); ffma2(num[1], pp0, vA.y);
      ffma2(num[2], pp0, vB.x); ffma2(num[3], pp0, vB.y);
      ffma2(num[4], pp0, vC.x); ffma2(num[5], pp0, vC.y);
      ffma2(num[6], pp0, vD.x); ffma2(num[7], pp0, vD.y);
    }
    __syncthreads();
  }

  // epilogue: o = num / den, stored to [b][n][h*16+hd]
  {
    float r = rcpf_(den); r = r*(2.0f - den*r);
    float4* o4 = (float4*)(g_O + ((size_t)b*NSEQ + q0)*ND + h*NHD);
    #pragma unroll
    for (int i=0;i<4;i++){
      float2 e0 = upk2(num[2*i]);
      float2 e1 = upk2(num[2*i+1]);
      o4[i] = make_float4(e0.x*r, e0.y*r, e1.x*r, e1.y*r);
    }
  }
}

// ---------------- launch -----------------------------------------------------
extern "C" void kernel_launch(void* const* d_in, const int* in_sizes, int n_in,
                              void* d_out, int out_size){
  const float* q    = (const float*)d_in[0];
  const float* k    = (const float*)d_in[1];
  const float* v    = (const float*)d_in[2];
  const float* Wq   = (const float*)d_in[3];
  const float* Wk   = (const float*)d_in[4];
  const float* Wv   = (const float*)d_in[5];
  const float* Wout = (const float*)d_in[6];
  const unsigned char* mask = (const unsigned char*)d_in[7];
  float* out = (float*)d_out;

  rope_table_kernel<<<16,128>>>();
  qkv_kernel<<<dim3(NROWS/64,1,3),128>>>(q,k,v,Wq,Wk,Wv);
  attn_kernel<<<dim3(NSEQ/128, NZH),128>>>(mask);
  outproj_kernel<<<dim3(NROWS/64,1,1),128>>>(Wout, out);
}

// round 3
// speedup vs baseline: 1.2096x; 1.1289x over previous
#include <cuda_runtime.h>
#include <cstdint>

#define NB   8
#define NSEQ 2048
#define ND   128
#define NH   8
#define NHD  16
#define NROWS (NB*NSEQ)     /* 16384 */
#define NZH   (NB*NH)       /* 64    */
#define NSPLIT 2
#define KEYS_PER_SPLIT (NSEQ/NSPLIT)   /* 1024 */
#define NTILES (KEYS_PER_SPLIT/128)    /* 8    */

// ---------------- scratch (device globals; no allocation allowed) -----------
__device__ float g_Q[NZH*NSEQ*NHD];     // Q after proj+rope, [b][h][n][hd]
__device__ float g_K[NZH*NSEQ*NHD];
__device__ float g_V[NZH*NSEQ*NHD];
__device__ float g_O[NROWS*ND];         // attention out, [b][n][h*hd]
__device__ float g_tab[NSEQ*8*3];       // per (n,j): cos, sin, scale
__device__ float g_pnum[NSPLIT*NZH*NSEQ*NHD];  // split-K partial numerators
__device__ float g_pden[NSPLIT*NZH*NSEQ];      // split-K partial denominators

// ---------------- tiny asm helpers -----------------------------------------
__device__ __forceinline__ unsigned long long pk2(float x, float y){
  unsigned long long r; asm("mov.b64 %0, {%1,%2};" : "=l"(r) : "f"(x), "f"(y)); return r; }
__device__ __forceinline__ float2 upk2(unsigned long long v){
  float2 r; asm("mov.b64 {%0,%1}, %2;" : "=f"(r.x), "=f"(r.y) : "l"(v)); return r; }
__device__ __forceinline__ void ffma2(unsigned long long& d, unsigned long long a, unsigned long long b){
  asm("fma.rn.f32x2 %0, %1, %2, %0;" : "+l"(d) : "l"(a), "l"(b)); }
__device__ __forceinline__ unsigned long long fadd2(unsigned long long a, unsigned long long b){
  unsigned long long r; asm("add.rn.f32x2 %0, %1, %2;" : "=l"(r) : "l"(a), "l"(b)); return r; }
__device__ __forceinline__ float ex2f_(float x){ float y; asm("ex2.approx.f32 %0, %1;" : "=f"(y) : "f"(x)); return y; }
__device__ __forceinline__ float rcpf_(float x){ float y; asm("rcp.approx.f32 %0, %1;" : "=f"(y) : "f"(x)); return y; }
__device__ __forceinline__ void cpasync16(uint32_t sdst, const void* gsrc){
  asm volatile("cp.async.cg.shared.global [%0], [%1], 16;" :: "r"(sdst), "l"(gsrc)); }
#define CP_COMMIT() asm volatile("cp.async.commit_group;")
#define CP_WAIT1()  asm volatile("cp.async.wait_group 1;")
#define CP_WAIT0()  asm volatile("cp.async.wait_group 0;")

// log(400)/log(50)/sqrt(16)
#define LOGIT_SCALE 0.38288786755f
#define LOG2E       1.4426950408889634f

// ---------------- rope tables (double precision, trivial cost) --------------
__global__ void rope_table_kernel(){
  int n = blockIdx.x*blockDim.x + threadIdx.x;
  if (n >= NSEQ) return;
  double t = (double)n;
  #pragma unroll
  for (int j=0;j<8;j++){
    double inv = exp(-((double)j/8.0) * log(10000.0));
    double f   = t * inv;
    double sc  = (2.0*j + 0.4*16.0) / (1.4*16.0);
    double pw  = (t - 1024.0) / 512.0;
    double scl = exp(pw * log(sc));
    int o = (n*8 + j)*3;
    g_tab[o+0] = (float)cos(f);
    g_tab[o+1] = (float)sin(f);
    g_tab[o+2] = (float)scl;
  }
}

// ---------------- tiled SGEMM: C[16384x128] = A[16384x128] @ W[128x128]^T ---
// MODE 0: row-major C.  MODE 1: scatter to [b][h][n][hd], rope: 0=none,1=Q,2=K.
template<int MODE>
__device__ __forceinline__ void gemm128(const float* __restrict__ A,
                                        const float* __restrict__ W,
                                        float* __restrict__ C, int rope){
  __shared__ float As[16][68];
  __shared__ float Ws[16][132];
  const int tid = threadIdx.x;
  const int m0  = blockIdx.x * 64;
  const int tm  = tid >> 4, tn = tid & 15;

  unsigned long long acc2[8][4];
  #pragma unroll
  for (int i=0;i<8;i++)
    #pragma unroll
    for (int j=0;j<4;j++) acc2[i][j]=0ull;

  const int ar = tid >> 1, ac = (tid & 1) * 8;
  for (int k0=0;k0<128;k0+=16){
    const float4* ap = (const float4*)(A + (size_t)(m0+ar)*128 + k0 + ac);
    float4 a0 = ap[0], a1 = ap[1];
    As[ac+0][ar]=a0.x; As[ac+1][ar]=a0.y; As[ac+2][ar]=a0.z; As[ac+3][ar]=a0.w;
    As[ac+4][ar]=a1.x; As[ac+5][ar]=a1.y; As[ac+6][ar]=a1.z; As[ac+7][ar]=a1.w;
    const float4* wp = (const float4*)(W + (size_t)tid*128 + k0);
    float4 w0=wp[0], w1=wp[1], w2=wp[2], w3=wp[3];
    Ws[ 0][tid]=w0.x; Ws[ 1][tid]=w0.y; Ws[ 2][tid]=w0.z; Ws[ 3][tid]=w0.w;
    Ws[ 4][tid]=w1.x; Ws[ 5][tid]=w1.y; Ws[ 6][tid]=w1.z; Ws[ 7][tid]=w1.w;
    Ws[ 8][tid]=w2.x; Ws[ 9][tid]=w2.y; Ws[10][tid]=w2.z; Ws[11][tid]=w2.w;
    Ws[12][tid]=w3.x; Ws[13][tid]=w3.y; Ws[14][tid]=w3.z; Ws[15][tid]=w3.w;
    __syncthreads();
    #pragma unroll
    for (int kk=0;kk<16;kk++){
      float av[8];
      #pragma unroll
      for (int i=0;i<8;i++) av[i] = As[kk][tm*8+i];
      const ulonglong2* wr = (const ulonglong2*)&Ws[kk][tn*8];
      ulonglong2 w01 = wr[0], w23 = wr[1];
      #pragma unroll
      for (int i=0;i<8;i++){
        unsigned long long aa = pk2(av[i], av[i]);
        ffma2(acc2[i][0], aa, w01.x);
        ffma2(acc2[i][1], aa, w01.y);
        ffma2(acc2[i][2], aa, w23.x);
        ffma2(acc2[i][3], aa, w23.y);
      }
    }
    __syncthreads();
  }

  if (MODE == 0){
    #pragma unroll
    for (int i=0;i<8;i++){
      int row = m0 + tm*8 + i;
      float2 e0=upk2(acc2[i][0]), e1=upk2(acc2[i][1]);
      float2 e2=upk2(acc2[i][2]), e3=upk2(acc2[i][3]);
      float4* c4 = (float4*)(C + (size_t)row*128 + tn*8);
      c4[0] = make_float4(e0.x,e0.y,e1.x,e1.y);
      c4[1] = make_float4(e2.x,e2.y,e3.x,e3.y);
    }
  } else {
    const int h = tn >> 1, hd0 = (tn & 1)*8;
    const int j0 = hd0 >> 1;              // first rope pair index (of 8)
    #pragma unroll
    for (int i=0;i<8;i++){
      int row = m0 + tm*8 + i;
      int bb = row >> 11, nn = row & 2047;
      float vbuf[8];
      {
        float2 e0=upk2(acc2[i][0]), e1=upk2(acc2[i][1]);
        float2 e2=upk2(acc2[i][2]), e3=upk2(acc2[i][3]);
        vbuf[0]=e0.x; vbuf[1]=e0.y; vbuf[2]=e1.x; vbuf[3]=e1.y;
        vbuf[4]=e2.x; vbuf[5]=e2.y; vbuf[6]=e3.x; vbuf[7]=e3.y;
      }
      if (rope != 0){
        const float* tb = g_tab + nn*24 + j0*3;
        #pragma unroll
        for (int jj=0;jj<4;jj++){
          float c=tb[jj*3+0], s=tb[jj*3+1], scl=tb[jj*3+2];
          float sc = (rope==1) ? scl : (1.0f/scl);
          float e=vbuf[2*jj], o=vbuf[2*jj+1];
          vbuf[2*jj]   = (e*c - o*s)*sc;
          vbuf[2*jj+1] = (o*c + e*s)*sc;
        }
      }
      float4* c4 = (float4*)(C + (((size_t)bb*NH + h)*NSEQ + nn)*NHD + hd0);
      c4[0] = make_float4(vbuf[0],vbuf[1],vbuf[2],vbuf[3]);
      c4[1] = make_float4(vbuf[4],vbuf[5],vbuf[6],vbuf[7]);
    }
  }
}

__global__ void __launch_bounds__(128) qkv_kernel(const float* __restrict__ q,
                                                  const float* __restrict__ k,
                                                  const float* __restrict__ v,
                                                  const float* __restrict__ Wq,
                                                  const float* __restrict__ Wk,
                                                  const float* __restrict__ Wv){
  int w = blockIdx.z;
  const float* A = (w==0) ? q  : (w==1) ? k  : v;
  const float* W = (w==0) ? Wq : (w==1) ? Wk : Wv;
  float*       C = (w==0) ? g_Q : (w==1) ? g_K : g_V;
  int rope = (w==0) ? 1 : (w==1) ? 2 : 0;
  gemm128<1>(A, W, C, rope);
}

__global__ void __launch_bounds__(128) outproj_kernel(const float* __restrict__ Wout,
                                                      float* __restrict__ out){
  gemm128<0>(g_O, Wout, out, 0);
}

// ---------------- attention: split-K, cp.async double-buffered ---------------
// grid ((NSEQ/128)*NSPLIT, NZH), 128 threads, 1 query/thread.
__global__ void __launch_bounds__(128) attn_kernel(const unsigned char* __restrict__ mask){
  const int z  = blockIdx.y;
  const int qt = blockIdx.x >> 1;
  const int sp = blockIdx.x & 1;
  const int t  = threadIdx.x;
  const int q0 = qt * 128 + t;
  const int kb0 = sp * KEYS_PER_SPLIT;
  const float* Qb = g_Q + (size_t)z * NSEQ * NHD;
  const float* Kb = g_K + (size_t)z * NSEQ * NHD;
  const float* Vb = g_V + (size_t)z * NSEQ * NHD;
  const unsigned char* mrow = mask + (z >> 3) * NSEQ;

  __shared__ float Ks[2][128*16];
  __shared__ float Vs[2][128*16];
  __shared__ float Msk[2][128];

  unsigned long long qp[8], num[8];
  {
    const ulonglong2* qa = (const ulonglong2*)(Qb + (size_t)q0*NHD);
    #pragma unroll
    for (int i=0;i<4;i++){ ulonglong2 u = qa[i]; qp[2*i]=u.x; qp[2*i+1]=u.y; }
  }
  #pragma unroll
  for (int i=0;i<8;i++) num[i]=0ull;
  float den=0.f;

  const float C_EX  = LOGIT_SCALE * 2.0f * LOG2E;  // ex2 arg per unit dot
  const float C_OUT = 10.0f * LOG2E;               // CLIP * log2(e)

  const uint32_t ks0 = (uint32_t)__cvta_generic_to_shared(&Ks[0][0]);
  const uint32_t ks1 = (uint32_t)__cvta_generic_to_shared(&Ks[1][0]);
  const uint32_t vs0 = (uint32_t)__cvta_generic_to_shared(&Vs[0][0]);
  const uint32_t vs1 = (uint32_t)__cvta_generic_to_shared(&Vs[1][0]);

  auto issue_tile = [&](int tile, int s){
    const float4* ksrc = (const float4*)(Kb + (size_t)(kb0 + tile*128)*NHD);
    const float4* vsrc = (const float4*)(Vb + (size_t)(kb0 + tile*128)*NHD);
    uint32_t kd = s ? ks1 : ks0;
    uint32_t vd = s ? vs1 : vs0;
    #pragma unroll
    for (int i=0;i<4;i++){
      int f = t + i*128;
      cpasync16(kd + f*16, ksrc + f);
      cpasync16(vd + f*16, vsrc + f);
    }
    Msk[s][t] = mrow[kb0 + tile*128 + t] ? 0.0f : 1.0f;
  };

  issue_tile(0, 0); CP_COMMIT();

  for (int tt=0; tt<NTILES; tt++){
    const int s = tt & 1;
    if (tt+1 < NTILES){ issue_tile(tt+1, s^1); CP_COMMIT(); CP_WAIT1(); }
    else              { CP_WAIT0(); }
    __syncthreads();   // tile tt landed and visible

    const float* kstile = Ks[s];
    const float* vstile = Vs[s];
    const float* mtile  = Msk[s];

    #pragma unroll 4
    for (int k=0;k<128;k++){
      const ulonglong2* kr2 = (const ulonglong2*)(kstile + k*16);
      ulonglong2 kA = kr2[0], kB = kr2[1], kC = kr2[2], kD = kr2[3];
      unsigned long long d0a=0ull, d0b=0ull;
      ffma2(d0a, qp[0], kA.x); ffma2(d0b, qp[1], kA.y);
      ffma2(d0a, qp[2], kB.x); ffma2(d0b, qp[3], kB.y);
      ffma2(d0a, qp[4], kC.x); ffma2(d0b, qp[5], kC.y);
      ffma2(d0a, qp[6], kD.x); ffma2(d0b, qp[7], kD.y);
      float2 f0 = upk2(fadd2(d0a, d0b));
      float dot0 = f0.x + f0.y;
      // p = exp(10 * tanh(dot * LOGIT_SCALE)); tanh via exact e^{2x} formula.
      float e0 = ex2f_(dot0 * C_EX);
      float r0 = rcpf_(e0 + 1.0f);
      float p0 = ex2f_(fmaf(r0, -2.0f*C_OUT, C_OUT)) * mtile[k];
      den += p0;
      const ulonglong2* vr2 = (const ulonglong2*)(vstile + k*16);
      ulonglong2 vA = vr2[0], vB = vr2[1], vC = vr2[2], vD = vr2[3];
      unsigned long long pp0 = pk2(p0,p0);
      ffma2(num[0], pp0, vA.x); ffma2(num[1], pp0, vA.y);
      ffma2(num[2], pp0, vB.x); ffma2(num[3], pp0, vB.y);
      ffma2(num[4], pp0, vC.x); ffma2(num[5], pp0, vC.y);
      ffma2(num[6], pp0, vD.x); ffma2(num[7], pp0, vD.y);
    }
    __syncthreads();   // all reads of stage s done before it is overwritten
  }

  // write split partials (no normalization yet)
  {
    const size_t pidx = ((size_t)sp*NZH + z)*NSEQ + q0;
    g_pden[pidx] = den;
    float4* pn = (float4*)(g_pnum + pidx*NHD);
    #pragma unroll
    for (int i=0;i<4;i++){
      float2 e0 = upk2(num[2*i]);
      float2 e1 = upk2(num[2*i+1]);
      pn[i] = make_float4(e0.x, e0.y, e1.x, e1.y);
    }
  }
}

// ---------------- merge split-K partials, normalize, scatter to g_O ----------
__global__ void __launch_bounds__(128) finalize_kernel(){
  const int idx = blockIdx.x*128 + threadIdx.x;   // z*NSEQ + q
  const int z = idx >> 11;
  const int q = idx & (NSEQ-1);
  const int b = z >> 3, h = z & 7;
  float den = g_pden[idx] + g_pden[NZH*NSEQ + idx];
  float r = rcpf_(den); r = r*(2.0f - den*r);
  const float4* n0 = (const float4*)(g_pnum + (size_t)idx*NHD);
  const float4* n1 = (const float4*)(g_pnum + ((size_t)NZH*NSEQ + idx)*NHD);
  float4* o4 = (float4*)(g_O + ((size_t)b*NSEQ + q)*ND + h*NHD);
  #pragma unroll
  for (int i=0;i<4;i++){
    float4 a = n0[i], c = n1[i];
    o4[i] = make_float4((a.x+c.x)*r, (a.y+c.y)*r, (a.z+c.z)*r, (a.w+c.w)*r);
  }
}

// ---------------- launch -----------------------------------------------------
extern "C" void kernel_launch(void* const* d_in, const int* in_sizes, int n_in,
                              void* d_out, int out_size){
  const float* q    = (const float*)d_in[0];
  const float* k    = (const float*)d_in[1];
  const float* v    = (const float*)d_in[2];
  const float* Wq   = (const float*)d_in[3];
  const float* Wk   = (const float*)d_in[4];
  const float* Wv   = (const float*)d_in[5];
  const float* Wout = (const float*)d_in[6];
  const unsigned char* mask = (const unsigned char*)d_in[7];
  float* out = (float*)d_out;

  rope_table_kernel<<<16,128>>>();
  qkv_kernel<<<dim3(NROWS/64,1,3),128>>>(q,k,v,Wq,Wk,Wv);
  attn_kernel<<<dim3((NSEQ/128)*NSPLIT, NZH),128>>>(mask);
  finalize_kernel<<<(NZH*NSEQ)/128,128>>>();
  outproj_kernel<<<dim3(NROWS/64,1,1),128>>>(Wout, out);
}

// round 6
// speedup vs baseline: 2.2114x; 1.8283x over previous
#include <cuda_runtime.h>
#include <cuda_fp16.h>
#include <cstdint>

#define NB   8
#define NSEQ 2048
#define ND   128
#define NH   8
#define NHD  16
#define NROWS (NB*NSEQ)     /* 16384 */
#define NZH   (NB*NH)       /* 64    */

// ---------------- scratch (device globals; no allocation allowed) -----------
__device__ float g_Q[NZH*NSEQ*NHD];     // Q after proj+rope, [b][h][n][hd]
__device__ float g_K[NZH*NSEQ*NHD];
__device__ float g_V[NZH*NSEQ*NHD];
__device__ float g_O[NROWS*ND];         // attention out, [b][n][h*hd]
__device__ float g_tab[NSEQ*8*3];       // per (n,j): cos, sin, scale

// ---------------- tiny asm helpers -----------------------------------------
__device__ __forceinline__ unsigned long long pk2(float x, float y){
  unsigned long long r; asm("mov.b64 %0, {%1,%2};" : "=l"(r) : "f"(x), "f"(y)); return r; }
__device__ __forceinline__ float2 upk2(unsigned long long v){
  float2 r; asm("mov.b64 {%0,%1}, %2;" : "=f"(r.x), "=f"(r.y) : "l"(v)); return r; }
__device__ __forceinline__ void ffma2(unsigned long long& d, unsigned long long a, unsigned long long b){
  asm("fma.rn.f32x2 %0, %1, %2, %0;" : "+l"(d) : "l"(a), "l"(b)); }
__device__ __forceinline__ float ex2f_(float x){ float y; asm("ex2.approx.f32 %0, %1;" : "=f"(y) : "f"(x)); return y; }
__device__ __forceinline__ float rcpf_(float x){ float y; asm("rcp.approx.f32 %0, %1;" : "=f"(y) : "f"(x)); return y; }

// pack two f32 -> f16x2 {lo, hi}.  PTX: first src -> upper half.
__device__ __forceinline__ uint32_t pkh2(float lo, float hi){
  uint32_t r; asm("cvt.rn.f16x2.f32 %0, %1, %2;" : "=r"(r) : "f"(hi), "f"(lo)); return r; }

// mma.m16n8k16 row.col f32 += f16 x f16 (accumulate in place)
__device__ __forceinline__ void mma16816(float* d, const uint32_t* a, uint32_t b0, uint32_t b1){
  asm volatile("mma.sync.aligned.m16n8k16.row.col.f32.f16.f16.f32 "
    "{%0,%1,%2,%3}, {%4,%5,%6,%7}, {%8,%9}, {%0,%1,%2,%3};"
    : "+f"(d[0]),"+f"(d[1]),"+f"(d[2]),"+f"(d[3])
    : "r"(a[0]),"r"(a[1]),"r"(a[2]),"r"(a[3]), "r"(b0),"r"(b1));
}

// log(400)/log(50)/sqrt(16)
#define LOGIT_SCALE 0.38288786755f
#define LOG2E       1.4426950408889634f
#define C_EX  (LOGIT_SCALE * 2.0f * LOG2E)
#define C_OUT (10.0f * LOG2E)

// p = exp(10*tanh(s*LOGIT_SCALE)), exact tanh via e^{2x}
__device__ __forceinline__ float pfun(float s){
  float e = ex2f_(s * C_EX);
  float r = rcpf_(e + 1.0f);
  return ex2f_(fmaf(r, -2.0f*C_OUT, C_OUT));
}

// ---------------- rope tables (double precision, trivial cost) --------------
__global__ void rope_table_kernel(){
  int n = blockIdx.x*blockDim.x + threadIdx.x;
  if (n >= NSEQ) return;
  double t = (double)n;
  #pragma unroll
  for (int j=0;j<8;j++){
    double inv = exp(-((double)j/8.0) * log(10000.0));
    double f   = t * inv;
    double sc  = (2.0*j + 0.4*16.0) / (1.4*16.0);
    double pw  = (t - 1024.0) / 512.0;
    double scl = exp(pw * log(sc));
    int o = (n*8 + j)*3;
    g_tab[o+0] = (float)cos(f);
    g_tab[o+1] = (float)sin(f);
    g_tab[o+2] = (float)scl;
  }
}

// ---------------- tiled SGEMM: C[16384x128] = A[16384x128] @ W[128x128]^T ---
template<int MODE>
__device__ __forceinline__ void gemm128(const float* __restrict__ A,
                                        const float* __restrict__ W,
                                        float* __restrict__ C, int rope){
  __shared__ float As[16][68];
  __shared__ float Ws[16][132];
  const int tid = threadIdx.x;
  const int m0  = blockIdx.x * 64;
  const int tm  = tid >> 4, tn = tid & 15;

  unsigned long long acc2[8][4];
  #pragma unroll
  for (int i=0;i<8;i++)
    #pragma unroll
    for (int j=0;j<4;j++) acc2[i][j]=0ull;

  const int ar = tid >> 1, ac = (tid & 1) * 8;
  for (int k0=0;k0<128;k0+=16){
    const float4* ap = (const float4*)(A + (size_t)(m0+ar)*128 + k0 + ac);
    float4 a0 = ap[0], a1 = ap[1];
    As[ac+0][ar]=a0.x; As[ac+1][ar]=a0.y; As[ac+2][ar]=a0.z; As[ac+3][ar]=a0.w;
    As[ac+4][ar]=a1.x; As[ac+5][ar]=a1.y; As[ac+6][ar]=a1.z; As[ac+7][ar]=a1.w;
    const float4* wp = (const float4*)(W + (size_t)tid*128 + k0);
    float4 w0=wp[0], w1=wp[1], w2=wp[2], w3=wp[3];
    Ws[ 0][tid]=w0.x; Ws[ 1][tid]=w0.y; Ws[ 2][tid]=w0.z; Ws[ 3][tid]=w0.w;
    Ws[ 4][tid]=w1.x; Ws[ 5][tid]=w1.y; Ws[ 6][tid]=w1.z; Ws[ 7][tid]=w1.w;
    Ws[ 8][tid]=w2.x; Ws[ 9][tid]=w2.y; Ws[10][tid]=w2.z; Ws[11][tid]=w2.w;
    Ws[12][tid]=w3.x; Ws[13][tid]=w3.y; Ws[14][tid]=w3.z; Ws[15][tid]=w3.w;
    __syncthreads();
    #pragma unroll
    for (int kk=0;kk<16;kk++){
      float av[8];
      #pragma unroll
      for (int i=0;i<8;i++) av[i] = As[kk][tm*8+i];
      const ulonglong2* wr = (const ulonglong2*)&Ws[kk][tn*8];
      ulonglong2 w01 = wr[0], w23 = wr[1];
      #pragma unroll
      for (int i=0;i<8;i++){
        unsigned long long aa = pk2(av[i], av[i]);
        ffma2(acc2[i][0], aa, w01.x);
        ffma2(acc2[i][1], aa, w01.y);
        ffma2(acc2[i][2], aa, w23.x);
        ffma2(acc2[i][3], aa, w23.y);
      }
    }
    __syncthreads();
  }

  if (MODE == 0){
    #pragma unroll
    for (int i=0;i<8;i++){
      int row = m0 + tm*8 + i;
      float2 e0=upk2(acc2[i][0]), e1=upk2(acc2[i][1]);
      float2 e2=upk2(acc2[i][2]), e3=upk2(acc2[i][3]);
      float4* c4 = (float4*)(C + (size_t)row*128 + tn*8);
      c4[0] = make_float4(e0.x,e0.y,e1.x,e1.y);
      c4[1] = make_float4(e2.x,e2.y,e3.x,e3.y);
    }
  } else {
    const int h = tn >> 1, hd0 = (tn & 1)*8;
    const int j0 = hd0 >> 1;
    #pragma unroll
    for (int i=0;i<8;i++){
      int row = m0 + tm*8 + i;
      int bb = row >> 11, nn = row & 2047;
      float vbuf[8];
      {
        float2 e0=upk2(acc2[i][0]), e1=upk2(acc2[i][1]);
        float2 e2=upk2(acc2[i][2]), e3=upk2(acc2[i][3]);
        vbuf[0]=e0.x; vbuf[1]=e0.y; vbuf[2]=e1.x; vbuf[3]=e1.y;
        vbuf[4]=e2.x; vbuf[5]=e2.y; vbuf[6]=e3.x; vbuf[7]=e3.y;
      }
      if (rope != 0){
        const float* tb = g_tab + nn*24 + j0*3;
        #pragma unroll
        for (int jj=0;jj<4;jj++){
          float c=tb[jj*3+0], s=tb[jj*3+1], scl=tb[jj*3+2];
          float sc = (rope==1) ? scl : (1.0f/scl);
          float e=vbuf[2*jj], o=vbuf[2*jj+1];
          vbuf[2*jj]   = (e*c - o*s)*sc;
          vbuf[2*jj+1] = (o*c + e*s)*sc;
        }
      }
      float4* c4 = (float4*)(C + (((size_t)bb*NH + h)*NSEQ + nn)*NHD + hd0);
      c4[0] = make_float4(vbuf[0],vbuf[1],vbuf[2],vbuf[3]);
      c4[1] = make_float4(vbuf[4],vbuf[5],vbuf[6],vbuf[7]);
    }
  }
}

__global__ void __launch_bounds__(128) qkv_kernel(const float* __restrict__ q,
                                                  const float* __restrict__ k,
                                                  const float* __restrict__ v,
                                                  const float* __restrict__ Wq,
                                                  const float* __restrict__ Wk,
                                                  const float* __restrict__ Wv){
  int w = blockIdx.z;
  const float* A = (w==0) ? q  : (w==1) ? k  : v;
  const float* W = (w==0) ? Wq : (w==1) ? Wk : Wv;
  float*       C = (w==0) ? g_Q : (w==1) ? g_K : g_V;
  int rope = (w==0) ? 1 : (w==1) ? 2 : 0;
  gemm128<1>(A, W, C, rope);
}

__global__ void __launch_bounds__(128) outproj_kernel(const float* __restrict__ Wout,
                                                      float* __restrict__ out){
  gemm128<0>(g_O, Wout, out, 0);
}

// ---------------- attention: fp16 mma.sync, split-fp16 QK, single pass ------
// grid (NSEQ/64, NZH), 128 threads (4 warps x 16 queries), 64-key tiles.
__global__ void __launch_bounds__(128) attn_kernel(const unsigned char* __restrict__ mask){
  const int z = blockIdx.y;
  const int b = z >> 3, h = z & 7;
  const int tid  = threadIdx.x;
  const int warp = tid >> 5, lane = tid & 31;
  const int g = lane >> 2, m = lane & 3;
  const int qb = blockIdx.x * 64 + warp * 16;
  const float* Qb = g_Q + (size_t)z*NSEQ*NHD;
  const float* Kb = g_K + (size_t)z*NSEQ*NHD;
  const float* Vb = g_V + (size_t)z*NSEQ*NHD;
  const unsigned char* mrow = mask + b*NSEQ;

  // smem: K split into fp16 hi/lo (stride 24 halves: bank-conflict-free B-frag
  // loads, word = 12g+m), V transposed fp16 [hd][key] stride 72 (word 4g+m).
  __shared__ __half KsHi[64][24];
  __shared__ __half KsLo[64][24];
  __shared__ __half VtS [16][72];
  __shared__ float  Ms[64];

  // ---- Q fragments (A of m16n8k16): split fp16 hi/lo, built once ----
  uint32_t qhi[4], qlo[4];
  {
    const float* r0 = Qb + (size_t)(qb+g)*NHD;
    const float* r8 = Qb + (size_t)(qb+g+8)*NHD;
    float2 xs[4];
    xs[0] = *(const float2*)(r0 + 2*m);
    xs[1] = *(const float2*)(r8 + 2*m);
    xs[2] = *(const float2*)(r0 + 2*m + 8);
    xs[3] = *(const float2*)(r8 + 2*m + 8);
    #pragma unroll
    for (int i=0;i<4;i++){
      __half2 hh = __floats2half2_rn(xs[i].x, xs[i].y);
      float2 bk = __half22float2(hh);
      __half2 ll = __floats2half2_rn(xs[i].x - bk.x, xs[i].y - bk.y);
      qhi[i] = *reinterpret_cast<uint32_t*>(&hh);
      qlo[i] = *reinterpret_cast<uint32_t*>(&ll);
    }
  }

  float o0[4] = {0,0,0,0};   // O[16q][hd 0..7]  fragment
  float o1[4] = {0,0,0,0};   // O[16q][hd 8..15] fragment
  float den0 = 0.f, den1 = 0.f;

  // ---- gmem tile prefetch registers (64 keys: K,V as 2 float4 per thread) ----
  const int c0r = tid >> 2,        c0f = (tid & 3) * 4;
  const int c1r = (tid+128) >> 2,  c1f = ((tid+128) & 3) * 4;
  float4 kr0, kr1, vr0, vr1; float mv = 1.f;

  auto prefetch = [&](int kt){
    kr0 = *(const float4*)(Kb + (size_t)(kt+c0r)*NHD + c0f);
    kr1 = *(const float4*)(Kb + (size_t)(kt+c1r)*NHD + c1f);
    vr0 = *(const float4*)(Vb + (size_t)(kt+c0r)*NHD + c0f);
    vr1 = *(const float4*)(Vb + (size_t)(kt+c1r)*NHD + c1f);
    if (tid < 64) mv = mrow[kt+tid] ? 0.0f : 1.0f;
  };
  auto sts_k = [&](int row, int col, float4 f){
    __half2 h01 = __floats2half2_rn(f.x, f.y);
    __half2 h23 = __floats2half2_rn(f.z, f.w);
    float2 b01 = __half22float2(h01);
    float2 b23 = __half22float2(h23);
    __half2 l01 = __floats2half2_rn(f.x-b01.x, f.y-b01.y);
    __half2 l23 = __floats2half2_rn(f.z-b23.x, f.w-b23.y);
    *reinterpret_cast<uint32_t*>(&KsHi[row][col  ]) = *reinterpret_cast<uint32_t*>(&h01);
    *reinterpret_cast<uint32_t*>(&KsHi[row][col+2]) = *reinterpret_cast<uint32_t*>(&h23);
    *reinterpret_cast<uint32_t*>(&KsLo[row][col  ]) = *reinterpret_cast<uint32_t*>(&l01);
    *reinterpret_cast<uint32_t*>(&KsLo[row][col+2]) = *reinterpret_cast<uint32_t*>(&l23);
  };
  auto sts_v = [&](int row, int col, float4 f){
    VtS[col+0][row] = __float2half_rn(f.x);
    VtS[col+1][row] = __float2half_rn(f.y);
    VtS[col+2][row] = __float2half_rn(f.z);
    VtS[col+3][row] = __float2half_rn(f.w);
  };

  prefetch(0);

  for (int kt=0; kt<NSEQ; kt+=64){
    sts_k(c0r, c0f, kr0); sts_k(c1r, c1f, kr1);
    sts_v(c0r, c0f, vr0); sts_v(c1r, c1f, vr1);
    if (tid < 64) Ms[tid] = mv;
    __syncthreads();
    if (kt + 64 < NSEQ) prefetch(kt + 64);

    #pragma unroll
    for (int kg=0; kg<64; kg+=16){
      // ---- QK^T: two 16x8 D tiles, 3 split MMAs each ----
      float dA[4] = {0,0,0,0}, dB[4] = {0,0,0,0};
      {
        uint32_t bh0 = *(const uint32_t*)&KsHi[kg+g][2*m];
        uint32_t bh1 = *(const uint32_t*)&KsHi[kg+g][2*m+8];
        uint32_t bl0 = *(const uint32_t*)&KsLo[kg+g][2*m];
        uint32_t bl1 = *(const uint32_t*)&KsLo[kg+g][2*m+8];
        mma16816(dA, qhi, bh0, bh1);
        mma16816(dA, qlo, bh0, bh1);
        mma16816(dA, qhi, bl0, bl1);
      }
      {
        uint32_t bh0 = *(const uint32_t*)&KsHi[kg+8+g][2*m];
        uint32_t bh1 = *(const uint32_t*)&KsHi[kg+8+g][2*m+8];
        uint32_t bl0 = *(const uint32_t*)&KsLo[kg+8+g][2*m];
        uint32_t bl1 = *(const uint32_t*)&KsLo[kg+8+g][2*m+8];
        mma16816(dB, qhi, bh0, bh1);
        mma16816(dB, qlo, bh0, bh1);
        mma16816(dB, qhi, bl0, bl1);
      }
      // ---- scores -> probs (exact tanh; masked) ----
      float mk0  = Ms[kg+2*m],   mk1  = Ms[kg+2*m+1];
      float mk0b = Ms[kg+8+2*m], mk1b = Ms[kg+8+2*m+1];
      float pA0 = pfun(dA[0])*mk0,  pA1 = pfun(dA[1])*mk1;
      float pA2 = pfun(dA[2])*mk0,  pA3 = pfun(dA[3])*mk1;
      float pB0 = pfun(dB[0])*mk0b, pB1 = pfun(dB[1])*mk1b;
      float pB2 = pfun(dB[2])*mk0b, pB3 = pfun(dB[3])*mk1b;
      den0 += (pA0 + pA1) + (pB0 + pB1);
      den1 += (pA2 + pA3) + (pB2 + pB3);
      // ---- pack P into A fragment (D->A identity, zero shuffles) ----
      uint32_t pa[4];
      pa[0] = pkh2(pA0, pA1);
      pa[1] = pkh2(pA2, pA3);
      pa[2] = pkh2(pB0, pB1);
      pa[3] = pkh2(pB2, pB3);
      // ---- PV: O += P[16x16] * V[16x16]  (two n8 tiles) ----
      {
        uint32_t vb0 = *(const uint32_t*)&VtS[g][kg+2*m];
        uint32_t vb1 = *(const uint32_t*)&VtS[g][kg+2*m+8];
        mma16816(o0, pa, vb0, vb1);
      }
      {
        uint32_t vb0 = *(const uint32_t*)&VtS[8+g][kg+2*m];
        uint32_t vb1 = *(const uint32_t*)&VtS[8+g][kg+2*m+8];
        mma16816(o1, pa, vb0, vb1);
      }
    }
    __syncthreads();
  }

  // ---- reduce den over the 4 lanes of each row group, normalize, store ----
  den0 += __shfl_xor_sync(0xffffffffu, den0, 1);
  den0 += __shfl_xor_sync(0xffffffffu, den0, 2);
  den1 += __shfl_xor_sync(0xffffffffu, den1, 1);
  den1 += __shfl_xor_sync(0xffffffffu, den1, 2);
  float rd0 = rcpf_(den0); rd0 = rd0*(2.0f - den0*rd0);
  float rd1 = rcpf_(den1); rd1 = rd1*(2.0f - den1*rd1);

  float* orow0 = g_O + ((size_t)b*NSEQ + qb + g    )*ND + h*NHD;
  float* orow8 = g_O + ((size_t)b*NSEQ + qb + g + 8)*ND + h*NHD;
  *(float2*)(orow0 + 2*m    ) = make_float2(o0[0]*rd0, o0[1]*rd0);
  *(float2*)(orow8 + 2*m    ) = make_float2(o0[2]*rd1, o0[3]*rd1);
  *(float2*)(orow0 + 2*m + 8) = make_float2(o1[0]*rd0, o1[1]*rd0);
  *(float2*)(orow8 + 2*m + 8) = make_float2(o1[2]*rd1, o1[3]*rd1);
}

// ---------------- launch -----------------------------------------------------
extern "C" void kernel_launch(void* const* d_in, const int* in_sizes, int n_in,
                              void* d_out, int out_size){
  const float* q    = (const float*)d_in[0];
  const float* k    = (const float*)d_in[1];
  const float* v    = (const float*)d_in[2];
  const float* Wq   = (const float*)d_in[3];
  const float* Wk   = (const float*)d_in[4];
  const float* Wv   = (const float*)d_in[5];
  const float* Wout = (const float*)d_in[6];
  const unsigned char* mask = (const unsigned char*)d_in[7];
  float* out = (float*)d_out;

  rope_table_kernel<<<16,128>>>();
  qkv_kernel<<<dim3(NROWS/64,1,3),128>>>(q,k,v,Wq,Wk,Wv);
  attn_kernel<<<dim3(NSEQ/64, NZH),128>>>(mask);
  outproj_kernel<<<dim3(NROWS/64,1,1),128>>>(Wout, out);
}